// round 5
// baseline (speedup 1.0000x reference)
#include <cuda_runtime.h>
#include <cuda_bf16.h>
#include <cstdint>

// ---------------------------------------------------------------------------
// out[t,o] = sum_i (x[t,i]*scales[i]) * W[o,i]
//   x [32,4096] f32, W [14336,4096] int32 (int8-valued), scales [4096] f32
//   out [32,14336] f32
//
// HMMA m16n8k16 bf16, xs split into bf16 hi+lo accumulated in fp32.
// R5: depth-2 W register prefetch (LDG issued 2 chunks ahead) + prep kernel
// fused with output zeroing. Split-K x2, 3 CTAs/SM, single barrier per chunk.
// ---------------------------------------------------------------------------

#define SWZ(off) ((off) ^ (((off) >> 3) & 0x70))

static constexpr int TOKENS = 32;
static constexpr int INF    = 4096;
static constexpr int OUTF   = 14336;
static constexpr int TILE_M = 64;
static constexpr int KSPLIT = 2;
static constexpr int KHALF  = INF / KSPLIT;     // 2048
static constexpr int KC     = 64;               // bf16 K elements per chunk
static constexpr int NITER  = KHALF / KC;       // 32

// per-buffer SMEM layout (bytes)
static constexpr int A_BYTES = TILE_M * 128;        // 8192 (64 rows x 128B, SW128)
static constexpr int B_BYTES = TOKENS * 128;        // 4096
static constexpr int BH_OFF  = A_BYTES;             // xs_hi
static constexpr int BL_OFF  = A_BYTES + B_BYTES;   // xs_lo
static constexpr int BUF_BYTES  = A_BYTES + 2 * B_BYTES;  // 16384
static constexpr int SMEM_TOTAL = 2 * BUF_BYTES;          // 32768

// split-bf16 scaled activations (built by prep kernel)
__device__ __nv_bfloat16 g_xs_hi[TOKENS * INF];
__device__ __nv_bfloat16 g_xs_lo[TOKENS * INF];

// ---------------- helpers ----------------
__device__ __forceinline__ uint32_t smem_u32(const void* p) {
    uint32_t a;
    asm("{ .reg .u64 t; cvta.to.shared.u64 t, %1; cvt.u32.u64 %0, t; }"
        : "=r"(a) : "l"(p));
    return a;
}

__device__ __forceinline__ void sts128(uint32_t addr, uint32_t r0, uint32_t r1,
                                       uint32_t r2, uint32_t r3) {
    asm volatile("st.shared.v4.b32 [%0], {%1, %2, %3, %4};"
                 :: "r"(addr), "r"(r0), "r"(r1), "r"(r2), "r"(r3) : "memory");
}

__device__ __forceinline__ void cp16(uint32_t dst, const void* src) {
    asm volatile("cp.async.cg.shared.global [%0], [%1], 16;"
                 :: "r"(dst), "l"(src) : "memory");
}
__device__ __forceinline__ void cp_commit() {
    asm volatile("cp.async.commit_group;" ::: "memory");
}
__device__ __forceinline__ void cp_wait0() {
    asm volatile("cp.async.wait_group 0;" ::: "memory");
}

// pack ints (int8-range, exact in bf16) -> bf16x2 {lo half = a, hi half = b}
__device__ __forceinline__ uint32_t packbf(int a, int b) {
    float fa = (float)a, fb = (float)b;
    uint32_t r;
    asm("cvt.rn.bf16x2.f32 %0, %1, %2;" : "=r"(r) : "f"(fb), "f"(fa));
    return r;
}

__device__ __forceinline__ void ldsm_x4(uint32_t addr, uint32_t& r0, uint32_t& r1,
                                        uint32_t& r2, uint32_t& r3) {
    asm volatile("ldmatrix.sync.aligned.m8n8.x4.shared.b16 {%0,%1,%2,%3}, [%4];"
                 : "=r"(r0), "=r"(r1), "=r"(r2), "=r"(r3) : "r"(addr));
}

__device__ __forceinline__ void mma_16816(float* d, const uint32_t* a, const uint32_t* b) {
    asm volatile(
        "mma.sync.aligned.m16n8k16.row.col.f32.bf16.bf16.f32 "
        "{%0,%1,%2,%3}, {%4,%5,%6,%7}, {%8,%9}, {%0,%1,%2,%3};"
        : "+f"(d[0]), "+f"(d[1]), "+f"(d[2]), "+f"(d[3])
        : "r"(a[0]), "r"(a[1]), "r"(a[2]), "r"(a[3]), "r"(b[0]), "r"(b[1]));
}

// ---------------- prep: xs split + zero the output (fused) ----------------
static constexpr int OUT_ELEMS = TOKENS * OUTF;        // 458752
static constexpr int OUT_VEC4  = OUT_ELEMS / 4;        // 114688

__global__ void prep_kernel(const float* __restrict__ x, const float* __restrict__ s,
                            float4* __restrict__ out4) {
    int i = blockIdx.x * blockDim.x + threadIdx.x;
    if (i < TOKENS * INF) {
        int k = i & (INF - 1);
        float v = x[i] * s[k];
        __nv_bfloat16 h = __float2bfloat16(v);
        g_xs_hi[i] = h;
        g_xs_lo[i] = __float2bfloat16(v - __bfloat162float(h));
    }
    if (i < OUT_VEC4) {
        out4[i] = make_float4(0.f, 0.f, 0.f, 0.f);
    }
}

// ---------------- main GEMM ----------------
__global__ void __launch_bounds__(256, 3)
qgemm_kernel(const int* __restrict__ W, float* __restrict__ out) {
    __shared__ __align__(1024) char smem[SMEM_TOTAL];
    const uint32_t sb = smem_u32(smem);
    const int tid = threadIdx.x;
    const int lane = tid & 31;
    const int wid = tid >> 5;
    const int rg = wid >> 1;     // row group 0..3 (16 rows each)
    const int th = wid & 1;      // token half 0..1 (16 tokens each)

    const int tile = blockIdx.x >> 1;
    const int kbase = (blockIdx.x & 1) * KHALF;
    const int row_base = tile * TILE_M;

    // ---- per-thread STS coordinates ----
    int wm[2], wg[2];
#pragma unroll
    for (int p = 0; p < 2; p++) {
        int gi = tid + p * 256;
        wm[p] = gi >> 3;     // 0..63 row
        wg[p] = gi & 7;      // 0..7 granule (8 weights)
    }
    int xt[2], xg[2], xarr[2];
#pragma unroll
    for (int q = 0; q < 2; q++) {
        int idx = tid + q * 256;
        xarr[q] = idx >> 8;
        int rem = idx & 255;
        xt[q] = rem >> 3;
        xg[q] = rem & 7;
    }

    // ---- ldmatrix lane geometry ----
    const int rowA  = rg * 16 + (lane & 7) + (lane & 8);
    const int aCsel = (lane & 16);              // +8 bf16 cols -> +16 bytes
    const int tokB  = th * 16 + (lane & 7) + ((lane & 16) >> 1);
    const int bCsel = (lane & 8) * 2;           // +16 bytes for k+8 tile

    float acc[2][4];
#pragma unroll
    for (int n = 0; n < 2; n++)
#pragma unroll
        for (int r = 0; r < 4; r++) acc[n][r] = 0.0f;

    int4 wreg[2][4];   // depth-2 register prefetch

    // ---- prologue: W chunks 0 and 1 into regs; xs chunk 0 via cp.async ----
#pragma unroll
    for (int p = 0; p < 2; p++) {
        const int4* ptr =
            (const int4*)(W + (size_t)(row_base + wm[p]) * INF + kbase + wg[p] * 8);
        wreg[0][2 * p]     = ptr[0];
        wreg[0][2 * p + 1] = ptr[1];
        const int4* ptr1 =
            (const int4*)(W + (size_t)(row_base + wm[p]) * INF + kbase + KC + wg[p] * 8);
        wreg[1][2 * p]     = ptr1[0];
        wreg[1][2 * p + 1] = ptr1[1];
    }
#pragma unroll
    for (int q = 0; q < 2; q++) {
        const __nv_bfloat16* src = xarr[q] ? g_xs_lo : g_xs_hi;
        cp16(sb + (xarr[q] ? BL_OFF : BH_OFF) + SWZ(xt[q] * 128 + xg[q] * 16),
             src + xt[q] * INF + kbase + xg[q] * 8);
    }
    cp_commit();

#pragma unroll 1
    for (int it = 0; it < NITER; ++it) {
        const uint32_t bufb = sb + (it & 1) * BUF_BYTES;
        int4* cur = wreg[it & 1];

        // ---- convert + store W tile (SW128); buf readers proven via sync(it-1) ----
#pragma unroll
        for (int p = 0; p < 2; p++) {
            int4 a0 = cur[2 * p], a1 = cur[2 * p + 1];
            uint32_t r0 = packbf(a0.x, a0.y);
            uint32_t r1 = packbf(a0.z, a0.w);
            uint32_t r2 = packbf(a1.x, a1.y);
            uint32_t r3 = packbf(a1.z, a1.w);
            sts128(bufb + SWZ(wm[p] * 128 + wg[p] * 16), r0, r1, r2, r3);
        }

        // ---- issue W LDGs for chunk it+2 (2 chunk-periods of latency cover) ----
        if (it + 2 < NITER) {
            const int k0 = kbase + (it + 2) * KC;
#pragma unroll
            for (int p = 0; p < 2; p++) {
                const int4* ptr =
                    (const int4*)(W + (size_t)(row_base + wm[p]) * INF + k0 + wg[p] * 8);
                cur[2 * p]     = ptr[0];
                cur[2 * p + 1] = ptr[1];
            }
        }

        cp_wait0();        // xs(it) landed
        __syncthreads();   // tile (it) visible; compute(it-1) done on all warps

        // ---- xs(it+1) cp.async into the other buffer (readers proven done) ----
        if (it + 1 < NITER) {
            const uint32_t nb = sb + ((it + 1) & 1) * BUF_BYTES;
            const int k0 = kbase + (it + 1) * KC;
#pragma unroll
            for (int q = 0; q < 2; q++) {
                const __nv_bfloat16* src = xarr[q] ? g_xs_lo : g_xs_hi;
                cp16(nb + (xarr[q] ? BL_OFF : BH_OFF) + SWZ(xt[q] * 128 + xg[q] * 16),
                     src + xt[q] * INF + k0 + xg[q] * 8);
            }
            cp_commit();
        }

        // ---- compute: 4 k16-steps, 2 n-groups, hi+lo into same fp32 acc ----
        const uint32_t sbh = bufb + BH_OFF;
        const uint32_t sbl = bufb + BL_OFF;
#pragma unroll
        for (int ks = 0; ks < 4; ks++) {
            uint32_t a[4], b[4];
            const int kb = ks * 32;

            ldsm_x4(bufb + SWZ(rowA * 128 + kb + aCsel), a[0], a[1], a[2], a[3]);

            const int bb = tokB * 128 + kb + bCsel;
            ldsm_x4(sbh + SWZ(bb), b[0], b[1], b[2], b[3]);
            mma_16816(acc[0], a, b + 0);
            mma_16816(acc[1], a, b + 2);
            ldsm_x4(sbl + SWZ(bb), b[0], b[1], b[2], b[3]);
            mma_16816(acc[0], a, b + 0);
            mma_16816(acc[1], a, b + 2);
        }
    }

    // ---- epilogue: atomicAdd partials (2 deterministic contributors/elem) ----
    const int g = lane >> 2;
    const int t2 = (lane & 3) * 2;
    const int f0 = row_base + rg * 16 + g;
#pragma unroll
    for (int nt = 0; nt < 2; nt++) {
        const int tok = th * 16 + nt * 8 + t2;
        atomicAdd(&out[(size_t)tok * OUTF + f0],           acc[nt][0]);
        atomicAdd(&out[(size_t)(tok + 1) * OUTF + f0],     acc[nt][1]);
        atomicAdd(&out[(size_t)tok * OUTF + f0 + 8],       acc[nt][2]);
        atomicAdd(&out[(size_t)(tok + 1) * OUTF + f0 + 8], acc[nt][3]);
    }
}

// ---------------- launch ----------------
extern "C" void kernel_launch(void* const* d_in, const int* in_sizes, int n_in,
                              void* d_out, int out_size) {
    const float* x      = (const float*)d_in[0];
    const int*   weight = (const int*)d_in[1];
    const float* scales = (const float*)d_in[2];
    float*       out    = (float*)d_out;
    (void)in_sizes; (void)n_in; (void)out_size;

    prep_kernel<<<(TOKENS * INF + 255) / 256, 256>>>(x, scales, (float4*)out);
    qgemm_kernel<<<(OUTF / TILE_M) * KSPLIT, 256>>>(weight, out);
}

// round 6
// speedup vs baseline: 1.4561x; 1.4561x over previous
#include <cuda_runtime.h>
#include <cuda_bf16.h>
#include <cstdint>

// ---------------------------------------------------------------------------
// out[t,o] = sum_i (x[t,i]*scales[i]) * W[o,i]
//   x [32,4096] f32, W [14336,4096] int32 (int8-valued), scales [4096] f32
//   out [32,14336] f32
//
// HMMA m16n8k16 bf16, xs split into bf16 hi+lo accumulated in fp32.
// R6: depth-2 W register prefetch via 2x-unrolled mainloop with NAMED register
// arrays (w0/w1, constant indexing only — R5's pointer indexing spilled to
// local memory and regressed). Split-K x2, 3 CTAs/SM, 1 barrier per chunk.
// ---------------------------------------------------------------------------

#define SWZ(off) ((off) ^ (((off) >> 3) & 0x70))

static constexpr int TOKENS = 32;
static constexpr int INF    = 4096;
static constexpr int OUTF   = 14336;
static constexpr int TILE_M = 64;
static constexpr int KSPLIT = 2;
static constexpr int KHALF  = INF / KSPLIT;     // 2048
static constexpr int KC     = 64;               // bf16 K elements per chunk
static constexpr int NITER  = KHALF / KC;       // 32 (even)
static constexpr int NPAIR  = NITER / 2;        // 16

// per-buffer SMEM layout (bytes)
static constexpr int A_BYTES = TILE_M * 128;        // 8192 (64 rows x 128B, SW128)
static constexpr int B_BYTES = TOKENS * 128;        // 4096
static constexpr int BH_OFF  = A_BYTES;             // xs_hi
static constexpr int BL_OFF  = A_BYTES + B_BYTES;   // xs_lo
static constexpr int BUF_BYTES  = A_BYTES + 2 * B_BYTES;  // 16384
static constexpr int SMEM_TOTAL = 2 * BUF_BYTES;          // 32768

// split-bf16 scaled activations (built by prep kernel)
__device__ __nv_bfloat16 g_xs_hi[TOKENS * INF];
__device__ __nv_bfloat16 g_xs_lo[TOKENS * INF];

// ---------------- helpers ----------------
__device__ __forceinline__ uint32_t smem_u32(const void* p) {
    uint32_t a;
    asm("{ .reg .u64 t; cvta.to.shared.u64 t, %1; cvt.u32.u64 %0, t; }"
        : "=r"(a) : "l"(p));
    return a;
}

__device__ __forceinline__ void sts128(uint32_t addr, uint32_t r0, uint32_t r1,
                                       uint32_t r2, uint32_t r3) {
    asm volatile("st.shared.v4.b32 [%0], {%1, %2, %3, %4};"
                 :: "r"(addr), "r"(r0), "r"(r1), "r"(r2), "r"(r3) : "memory");
}

__device__ __forceinline__ void cp16(uint32_t dst, const void* src) {
    asm volatile("cp.async.cg.shared.global [%0], [%1], 16;"
                 :: "r"(dst), "l"(src) : "memory");
}
__device__ __forceinline__ void cp_commit() {
    asm volatile("cp.async.commit_group;" ::: "memory");
}
__device__ __forceinline__ void cp_wait0() {
    asm volatile("cp.async.wait_group 0;" ::: "memory");
}

// pack ints (int8-range, exact in bf16) -> bf16x2 {lo half = a, hi half = b}
__device__ __forceinline__ uint32_t packbf(int a, int b) {
    float fa = (float)a, fb = (float)b;
    uint32_t r;
    asm("cvt.rn.bf16x2.f32 %0, %1, %2;" : "=r"(r) : "f"(fb), "f"(fa));
    return r;
}

__device__ __forceinline__ void ldsm_x4(uint32_t addr, uint32_t& r0, uint32_t& r1,
                                        uint32_t& r2, uint32_t& r3) {
    asm volatile("ldmatrix.sync.aligned.m8n8.x4.shared.b16 {%0,%1,%2,%3}, [%4];"
                 : "=r"(r0), "=r"(r1), "=r"(r2), "=r"(r3) : "r"(addr));
}

__device__ __forceinline__ void mma_16816(float* d, const uint32_t* a, const uint32_t* b) {
    asm volatile(
        "mma.sync.aligned.m16n8k16.row.col.f32.bf16.bf16.f32 "
        "{%0,%1,%2,%3}, {%4,%5,%6,%7}, {%8,%9}, {%0,%1,%2,%3};"
        : "+f"(d[0]), "+f"(d[1]), "+f"(d[2]), "+f"(d[3])
        : "r"(a[0]), "r"(a[1]), "r"(a[2]), "r"(a[3]), "r"(b[0]), "r"(b[1]));
}

// ---------------- prep: xs split + zero the output (fused) ----------------
static constexpr int OUT_ELEMS = TOKENS * OUTF;        // 458752
static constexpr int OUT_VEC4  = OUT_ELEMS / 4;        // 114688

__global__ void prep_kernel(const float* __restrict__ x, const float* __restrict__ s,
                            float4* __restrict__ out4) {
    int i = blockIdx.x * blockDim.x + threadIdx.x;
    if (i < TOKENS * INF) {
        int k = i & (INF - 1);
        float v = x[i] * s[k];
        __nv_bfloat16 h = __float2bfloat16(v);
        g_xs_hi[i] = h;
        g_xs_lo[i] = __float2bfloat16(v - __bfloat162float(h));
    }
    if (i < OUT_VEC4) {
        out4[i] = make_float4(0.f, 0.f, 0.f, 0.f);
    }
}

// ---------------- main GEMM ----------------
__global__ void __launch_bounds__(256, 3)
qgemm_kernel(const int* __restrict__ W, float* __restrict__ out) {
    __shared__ __align__(1024) char smem[SMEM_TOTAL];
    const uint32_t sb = smem_u32(smem);
    const int tid = threadIdx.x;
    const int lane = tid & 31;
    const int wid = tid >> 5;
    const int rg = wid >> 1;     // row group 0..3 (16 rows each)
    const int th = wid & 1;      // token half 0..1 (16 tokens each)

    const int tile = blockIdx.x >> 1;
    const int kbase = (blockIdx.x & 1) * KHALF;
    const int row_base = tile * TILE_M;

    // ---- W producer coordinates: 2 granules of 8 int32 per thread ----
    const int4* wp0;
    const int4* wp1;
    uint32_t wsts0, wsts1;
    {
        int g0 = tid;            // granule 0..255
        int g1 = tid + 256;      // granule 256..511
        int m0 = g0 >> 3, c0 = g0 & 7;
        int m1 = g1 >> 3, c1 = g1 & 7;
        wp0 = (const int4*)(W + (size_t)(row_base + m0) * INF + kbase + c0 * 8);
        wp1 = (const int4*)(W + (size_t)(row_base + m1) * INF + kbase + c1 * 8);
        wsts0 = SWZ(m0 * 128 + c0 * 16);
        wsts1 = SWZ(m1 * 128 + c1 * 16);
    }
    // ---- xs producer coordinates ----
    const char* xp0;
    const char* xp1;
    uint32_t xsts0, xsts1;   // offset within buffer (incl BH/BL)
    {
        int t0 = tid >> 3,          c0 = tid & 7;            // hi array
        int t1 = (tid & 255) >> 3,  c1 = tid & 7;            // lo array
        xp0 = (const char*)(g_xs_hi + t0 * INF + kbase + c0 * 8);
        xp1 = (const char*)(g_xs_lo + t1 * INF + kbase + c1 * 8);
        xsts0 = BH_OFF + SWZ(t0 * 128 + c0 * 16);
        xsts1 = BL_OFF + SWZ(t1 * 128 + c1 * 16);
    }

    // ---- ldmatrix lane geometry ----
    const int rowA  = rg * 16 + (lane & 7) + (lane & 8);
    const int aCsel = (lane & 16);              // +8 bf16 cols -> +16 bytes
    const int tokB  = th * 16 + (lane & 7) + ((lane & 16) >> 1);
    const int bCsel = (lane & 8) * 2;           // +16 bytes for k+8 tile
    const uint32_t aAddrOff = SWZ(rowA * 128 + aCsel);
    const uint32_t bAddrOff = SWZ(tokB * 128 + bCsel);  // SWZ is XOR in low 7 bits of
    // NOTE: SWZ mixes bits [9:7] into [6:4]; adding kb (multiple of 32, bits>=5)
    // does not commute with SWZ, so compute SWZ(full) per step below instead.

    float acc[2][4];
#pragma unroll
    for (int n = 0; n < 2; n++)
#pragma unroll
        for (int r = 0; r < 4; r++) acc[n][r] = 0.0f;

    // depth-2 W staging: NAMED arrays, constant indices only
    int4 w0[4], w1[4];

    // ---- prologue: W chunks 0,1 -> regs; xs chunk 0 -> cp.async ----
    w0[0] = wp0[0]; w0[1] = wp0[1];
    w0[2] = wp1[0]; w0[3] = wp1[1];
    wp0 += 16; wp1 += 16;                      // +KC ints
    w1[0] = wp0[0]; w1[1] = wp0[1];
    w1[2] = wp1[0]; w1[3] = wp1[1];
    wp0 += 16; wp1 += 16;

    cp16(sb + xsts0, xp0); xp0 += KC * 2;
    cp16(sb + xsts1, xp1); xp1 += KC * 2;
    cp_commit();

    const uint32_t buf0 = sb;
    const uint32_t buf1 = sb + BUF_BYTES;

#pragma unroll 1
    for (int itp = 0; itp < NPAIR; ++itp) {
        // ================= even chunk e = 2*itp, buffer 0 =================
        {
            // convert + store w0 -> buf0
            uint32_t r0 = packbf(w0[0].x, w0[0].y), r1 = packbf(w0[0].z, w0[0].w);
            uint32_t r2 = packbf(w0[1].x, w0[1].y), r3 = packbf(w0[1].z, w0[1].w);
            sts128(buf0 + wsts0, r0, r1, r2, r3);
            r0 = packbf(w0[2].x, w0[2].y); r1 = packbf(w0[2].z, w0[2].w);
            r2 = packbf(w0[3].x, w0[3].y); r3 = packbf(w0[3].z, w0[3].w);
            sts128(buf0 + wsts1, r0, r1, r2, r3);

            // refill w0 from chunk e+2 (consumed 2 chunk-periods from now)
            if (itp + 1 < NPAIR) {
                w0[0] = wp0[0]; w0[1] = wp0[1];
                w0[2] = wp1[0]; w0[3] = wp1[1];
                wp0 += 16; wp1 += 16;
            }

            cp_wait0();        // xs(e) landed in buf0
            __syncthreads();   // buf0 tile visible; prior buf1 readers done

            // xs(e+1) -> buf1
            cp16(buf1 + xsts0, xp0); xp0 += KC * 2;
            cp16(buf1 + xsts1, xp1); xp1 += KC * 2;
            cp_commit();

            // compute buf0
#pragma unroll
            for (int ks = 0; ks < 4; ks++) {
                uint32_t a[4], b[4];
                const int kb = ks * 32;
                ldsm_x4(buf0 + SWZ(rowA * 128 + kb + aCsel), a[0], a[1], a[2], a[3]);
                const int bb = tokB * 128 + kb + bCsel;
                ldsm_x4(buf0 + BH_OFF + SWZ(bb), b[0], b[1], b[2], b[3]);
                mma_16816(acc[0], a, b + 0);
                mma_16816(acc[1], a, b + 2);
                ldsm_x4(buf0 + BL_OFF + SWZ(bb), b[0], b[1], b[2], b[3]);
                mma_16816(acc[0], a, b + 0);
                mma_16816(acc[1], a, b + 2);
            }
        }
        // ================= odd chunk o = e+1, buffer 1 =================
        {
            // convert + store w1 -> buf1 (prior buf1 compute proven done by the
            // even-half __syncthreads above)
            uint32_t r0 = packbf(w1[0].x, w1[0].y), r1 = packbf(w1[0].z, w1[0].w);
            uint32_t r2 = packbf(w1[1].x, w1[1].y), r3 = packbf(w1[1].z, w1[1].w);
            sts128(buf1 + wsts0, r0, r1, r2, r3);
            r0 = packbf(w1[2].x, w1[2].y); r1 = packbf(w1[2].z, w1[2].w);
            r2 = packbf(w1[3].x, w1[3].y); r3 = packbf(w1[3].z, w1[3].w);
            sts128(buf1 + wsts1, r0, r1, r2, r3);

            // refill w1 from chunk o+2
            if (itp + 1 < NPAIR) {
                w1[0] = wp0[0]; w1[1] = wp0[1];
                w1[2] = wp1[0]; w1[3] = wp1[1];
                wp0 += 16; wp1 += 16;
            }

            cp_wait0();        // xs(o) landed in buf1
            __syncthreads();   // buf1 tile visible; buf0 readers done

            // xs(o+1) -> buf0
            if (itp + 1 < NPAIR) {
                cp16(buf0 + xsts0, xp0); xp0 += KC * 2;
                cp16(buf0 + xsts1, xp1); xp1 += KC * 2;
                cp_commit();
            }

            // compute buf1
#pragma unroll
            for (int ks = 0; ks < 4; ks++) {
                uint32_t a[4], b[4];
                const int kb = ks * 32;
                ldsm_x4(buf1 + SWZ(rowA * 128 + kb + aCsel), a[0], a[1], a[2], a[3]);
                const int bb = tokB * 128 + kb + bCsel;
                ldsm_x4(buf1 + BH_OFF + SWZ(bb), b[0], b[1], b[2], b[3]);
                mma_16816(acc[0], a, b + 0);
                mma_16816(acc[1], a, b + 2);
                ldsm_x4(buf1 + BL_OFF + SWZ(bb), b[0], b[1], b[2], b[3]);
                mma_16816(acc[0], a, b + 0);
                mma_16816(acc[1], a, b + 2);
            }
        }
    }

    // ---- epilogue: atomicAdd partials (2 deterministic contributors/elem) ----
    const int g = lane >> 2;
    const int t2 = (lane & 3) * 2;
    const int f0 = row_base + rg * 16 + g;
#pragma unroll
    for (int nt = 0; nt < 2; nt++) {
        const int tok = th * 16 + nt * 8 + t2;
        atomicAdd(&out[(size_t)tok * OUTF + f0],           acc[nt][0]);
        atomicAdd(&out[(size_t)(tok + 1) * OUTF + f0],     acc[nt][1]);
        atomicAdd(&out[(size_t)tok * OUTF + f0 + 8],       acc[nt][2]);
        atomicAdd(&out[(size_t)(tok + 1) * OUTF + f0 + 8], acc[nt][3]);
    }
}

// ---------------- launch ----------------
extern "C" void kernel_launch(void* const* d_in, const int* in_sizes, int n_in,
                              void* d_out, int out_size) {
    const float* x      = (const float*)d_in[0];
    const int*   weight = (const int*)d_in[1];
    const float* scales = (const float*)d_in[2];
    float*       out    = (float*)d_out;
    (void)in_sizes; (void)n_in; (void)out_size;

    prep_kernel<<<(TOKENS * INF + 255) / 256, 256>>>(x, scales, (float4*)out);
    qgemm_kernel<<<(OUTF / TILE_M) * KSPLIT, 256>>>(weight, out);
}